// round 4
// baseline (speedup 1.0000x reference)
#include <cuda_runtime.h>

#define NN 100000
#define NE 1250000
#define D  64
#define EF 13

// ---------------- scratch (device globals; no allocation allowed) ----------------
__device__ float g_sm[EF];
__device__ int   g_is64;
__device__ int   g_rows[NE];
__device__ int   g_cols[NE];
__device__ float g_ew[NE];
__device__ float g_norm[NE];
__device__ float g_deg[NN];
__device__ float g_dinv[NN];
__device__ float g_dsq[NN];
__device__ __align__(16) float g_h[NN * D];     // GEMM output (per layer)
__device__ __align__(16) float g_agg[NN * D];   // scatter destination (per layer)
__device__ __align__(16) float g_bufA[NN * D];  // x1 / x3
__device__ __align__(16) float g_bufB[NN * D];  // x2
__device__ float g_S[3 * D];      // pool numerators
__device__ float g_Z[3];          // pool denominators

// ---------------- init: softmax(aaaaa), zero pool accs, detect index dtype -------
__global__ void k_init(const float* __restrict__ aaaaa,
                       const int* __restrict__ ei_raw) {
    int t = threadIdx.x;
    if (t < 3 * D) g_S[t] = 0.0f;
    if (t < 3)     g_Z[t] = 0.0f;
    if (t == 0) {
        float v[EF];
        float m = -1e30f;
        for (int j = 0; j < EF; j++) { v[j] = aaaaa[j]; m = fmaxf(m, v[j]); }
        float s = 0.0f;
        for (int j = 0; j < EF; j++) { v[j] = expf(v[j] - m); s += v[j]; }
        for (int j = 0; j < EF; j++) g_sm[j] = v[j] / s;

        // dtype sniff: if edge_index is int64, every odd 32-bit word (high half)
        // of the first 64 entries is 0 (indices are small non-negative).
        int is64 = 1;
        for (int i = 0; i < 64; i++) {
            if (ei_raw[2 * i + 1] != 0) { is64 = 0; break; }
        }
        g_is64 = is64;
    }
}

// ---------------- decode edge_index into int32 rows/cols --------------------------
__global__ void k_decode(const void* __restrict__ ei, int E) {
    int e = blockIdx.x * blockDim.x + threadIdx.x;
    if (e >= E) return;
    if (g_is64) {
        const long long* p = (const long long*)ei;
        g_rows[e] = (int)p[e];
        g_cols[e] = (int)p[E + e];
    } else {
        const int* p = (const int*)ei;
        g_rows[e] = p[e];
        g_cols[e] = p[E + e];
    }
}

// ---------------- degree init (self-loop weight 1.0) -----------------------------
__global__ void k_deginit(int n) {
    int i = blockIdx.x * blockDim.x + threadIdx.x;
    if (i < n) g_deg[i] = 1.0f;
}

// ---------------- edge weight + degree accumulation ------------------------------
__global__ void k_ewdeg(const float* __restrict__ ea, int E) {
    int e = blockIdx.x * blockDim.x + threadIdx.x;
    if (e >= E) return;
    float s = 0.0f;
    const float* row = ea + (long long)e * EF;
#pragma unroll
    for (int j = 0; j < EF; j++) s += row[j] * g_sm[j];
    g_ew[e] = s;
    atomicAdd(&g_deg[g_cols[e]], s);
}

// ---------------- deg^{-1/2} and self-loop norm -----------------------------------
__global__ void k_dinv(int n) {
    int i = blockIdx.x * blockDim.x + threadIdx.x;
    if (i >= n) return;
    float d = g_deg[i];               // >= 1 always (self loop)
    float di = rsqrtf(d);
    g_dinv[i] = di;
    g_dsq[i] = di * di;
}

// ---------------- edge norm ------------------------------------------------------
__global__ void k_norm(int E) {
    int e = blockIdx.x * blockDim.x + threadIdx.x;
    if (e >= E) return;
    g_norm[e] = g_dinv[g_rows[e]] * g_ew[e] * g_dinv[g_cols[e]];
}

// ---------------- GEMM: h = x @ W  (thread per row, W in smem) --------------------
__global__ void k_gemm(const float* __restrict__ xext, int sel,
                       const float* __restrict__ W, int n) {
    __shared__ float Ws[D * D];
    for (int i = threadIdx.x; i < D * D; i += blockDim.x) Ws[i] = W[i];
    __syncthreads();

    const float* x = (sel == 0) ? xext : ((sel == 1) ? g_bufA : g_bufB);
    int row = blockIdx.x * blockDim.x + threadIdx.x;
    if (row >= n) return;

    const float4* xr = (const float4*)(x + (long long)row * D);
    float4 acc[16];
#pragma unroll
    for (int c = 0; c < 16; c++) acc[c] = make_float4(0.f, 0.f, 0.f, 0.f);

#pragma unroll
    for (int k4 = 0; k4 < 16; k4++) {
        float4 xv = xr[k4];
        float xa[4] = {xv.x, xv.y, xv.z, xv.w};
#pragma unroll
        for (int kk = 0; kk < 4; kk++) {
            float xk = xa[kk];
            const float4* wrow = (const float4*)&Ws[(k4 * 4 + kk) * D];
#pragma unroll
            for (int c = 0; c < 16; c++) {
                float4 wv = wrow[c];
                acc[c].x += xk * wv.x;
                acc[c].y += xk * wv.y;
                acc[c].z += xk * wv.z;
                acc[c].w += xk * wv.w;
            }
        }
    }
    float4* ho = (float4*)(g_h + (long long)row * D);
#pragma unroll
    for (int c = 0; c < 16; c++) ho[c] = acc[c];
}

// ---------------- zero the aggregation buffer -------------------------------------
__global__ void k_zero(int n4) {
    int i = blockIdx.x * blockDim.x + threadIdx.x;
    if (i < n4) ((float4*)g_agg)[i] = make_float4(0.f, 0.f, 0.f, 0.f);
}

// ---------------- scatter-add: agg[col] += norm * h[row], vector atomics ----------
__global__ void k_scatter(int E) {
    int t = blockIdx.x * blockDim.x + threadIdx.x;
    if (t >= E * 16) return;
    int e  = t >> 4;
    int c4 = t & 15;
    float ne = __ldg(&g_norm[e]);
    int r = __ldg(&g_rows[e]);
    int c = __ldg(&g_cols[e]);
    float4 hv = *(const float4*)&g_h[r * D + c4 * 4];
    float* dst = &g_agg[c * D + c4 * 4];
    asm volatile("red.global.add.v4.f32 [%0], {%1,%2,%3,%4};"
                 :: "l"(dst), "f"(ne * hv.x), "f"(ne * hv.y),
                    "f"(ne * hv.z), "f"(ne * hv.w)
                 : "memory");
}

// ---------------- finalize (+self loop, +bias, relu) + attention pool -------------
// warp per node; register-accumulated pool partials; 3 global atomics per warp.
__global__ void k_finpool(int sel_out, const float* __restrict__ b,
                          const float* __restrict__ wg,
                          const float* __restrict__ bg,
                          int layer, int n) {
    float* xo = (sel_out == 1) ? g_bufA : g_bufB;
    int lane = threadIdx.x & 31;
    int warp = (blockIdx.x * blockDim.x + threadIdx.x) >> 5;
    int nwarps = (gridDim.x * blockDim.x) >> 5;

    float wg0 = wg[lane], wg1 = wg[lane + 32];
    float b0 = b[lane],  b1 = b[lane + 32];
    float bgv = bg[0];

    float s0 = 0.f, s1 = 0.f, z = 0.f;

    for (int i = warp; i < n; i += nwarps) {
        int idx = i * D + lane;
        float ds = g_dsq[i];
        float v0 = g_agg[idx]      + ds * g_h[idx]      + b0;
        float v1 = g_agg[idx + 32] + ds * g_h[idx + 32] + b1;
        v0 = fmaxf(v0, 0.f);
        v1 = fmaxf(v1, 0.f);
        xo[idx] = v0;
        xo[idx + 32] = v1;

        float dot = v0 * wg0 + v1 * wg1;
#pragma unroll
        for (int off = 16; off > 0; off >>= 1)
            dot += __shfl_xor_sync(0xffffffffu, dot, off);
        float g = dot + bgv;
        float sg = 1.0f / (1.0f + expf(-g));   // sigmoid gate
        float w = expf(sg);                    // softmax numerator over nodes
        s0 += w * v0;
        s1 += w * v1;
        if (lane == 0) z += w;
    }
    atomicAdd(&g_S[layer * D + lane], s0);
    atomicAdd(&g_S[layer * D + lane + 32], s1);
    if (lane == 0) atomicAdd(&g_Z[layer], z);
}

// ---------------- final divide ----------------------------------------------------
__global__ void k_out(float* __restrict__ out) {
    int t = threadIdx.x;
    if (t < 3 * D) out[t] = g_S[t] / g_Z[t / D];
}

// ---------------- launch ----------------------------------------------------------
extern "C" void kernel_launch(void* const* d_in, const int* in_sizes, int n_in,
                              void* d_out, int out_size) {
    const float* x     = (const float*)d_in[0];
    const void*  ei    = d_in[1];
    const float* ea    = (const float*)d_in[2];
    const float* aaaaa = (const float*)d_in[3];
    const float* W[3]  = {(const float*)d_in[4], (const float*)d_in[6], (const float*)d_in[8]};
    const float* b[3]  = {(const float*)d_in[5], (const float*)d_in[7], (const float*)d_in[9]};
    const float* wg[3] = {(const float*)d_in[10], (const float*)d_in[12], (const float*)d_in[14]};
    const float* bg[3] = {(const float*)d_in[11], (const float*)d_in[13], (const float*)d_in[15]};
    float* out = (float*)d_out;

    int N = in_sizes[0] / D;     // 100000
    int E = in_sizes[2] / EF;    // 1250000

    k_init<<<1, 256>>>(aaaaa, (const int*)ei);
    k_decode<<<(E + 255) / 256, 256>>>(ei, E);
    k_deginit<<<(N + 255) / 256, 256>>>(N);
    k_ewdeg<<<(E + 255) / 256, 256>>>(ea, E);
    k_dinv<<<(N + 255) / 256, 256>>>(N);
    k_norm<<<(E + 255) / 256, 256>>>(E);

    int n4 = N * D / 4;
    // layer 1: x(ext) -> bufA, pool 0
    k_gemm<<<(N + 127) / 128, 128>>>(x, 0, W[0], N);
    k_zero<<<(n4 + 255) / 256, 256>>>(n4);
    k_scatter<<<(E * 16 + 255) / 256, 256>>>(E);
    k_finpool<<<512, 256>>>(1, b[0], wg[0], bg[0], 0, N);
    // layer 2: bufA -> bufB, pool 1
    k_gemm<<<(N + 127) / 128, 128>>>(x, 1, W[1], N);
    k_zero<<<(n4 + 255) / 256, 256>>>(n4);
    k_scatter<<<(E * 16 + 255) / 256, 256>>>(E);
    k_finpool<<<512, 256>>>(2, b[1], wg[1], bg[1], 1, N);
    // layer 3: bufB -> bufA, pool 2
    k_gemm<<<(N + 127) / 128, 128>>>(x, 2, W[2], N);
    k_zero<<<(n4 + 255) / 256, 256>>>(n4);
    k_scatter<<<(E * 16 + 255) / 256, 256>>>(E);
    k_finpool<<<512, 256>>>(1, b[2], wg[2], bg[2], 2, N);

    k_out<<<1, 192>>>(out);
}

// round 5
// speedup vs baseline: 1.2878x; 1.2878x over previous
#include <cuda_runtime.h>

#define NN 100000
#define NE 1250000
#define D  64
#define EF 13
#define SCAN_B 1024

// ---------------- scratch (device globals; no allocation allowed) ----------------
__device__ float g_sm[EF];
__device__ int   g_is64;
__device__ int   g_rows[NE];
__device__ int   g_cols[NE];
__device__ float g_ew[NE];
__device__ float g_deg[NN];
__device__ float g_dinv[NN];
__device__ float g_dsq[NN];
__device__ int   g_cnt[NN];       // in-degree (edge count per dest)
__device__ int   g_start[NN];     // CSR offsets
__device__ int   g_cursor[NN];    // build cursors
__device__ int   g_bsum[128];     // scan partials
__device__ int   g_boff[128];
__device__ __align__(16) uint2 g_edge[NE];      // packed (row, norm) sorted by col
__device__ __align__(16) float g_h[NN * D];     // GEMM output (per layer)
__device__ __align__(16) float g_bufA[NN * D];  // x1 / x3
__device__ __align__(16) float g_bufB[NN * D];  // x2
__device__ float g_S[3 * D];      // pool numerators
__device__ float g_Z[3];          // pool denominators

// ---------------- init: softmax(aaaaa), zero pool accs, detect index dtype -------
__global__ void k_init(const float* __restrict__ aaaaa,
                       const int* __restrict__ ei_raw) {
    int t = threadIdx.x;
    if (t < 3 * D) g_S[t] = 0.0f;
    if (t < 3)     g_Z[t] = 0.0f;
    if (t == 0) {
        float v[EF];
        float m = -1e30f;
        for (int j = 0; j < EF; j++) { v[j] = aaaaa[j]; m = fmaxf(m, v[j]); }
        float s = 0.0f;
        for (int j = 0; j < EF; j++) { v[j] = expf(v[j] - m); s += v[j]; }
        for (int j = 0; j < EF; j++) g_sm[j] = v[j] / s;

        // dtype sniff: int64 indices have zero high words
        int is64 = 1;
        for (int i = 0; i < 64; i++)
            if (ei_raw[2 * i + 1] != 0) { is64 = 0; break; }
        g_is64 = is64;
    }
}

// ---------------- decode edge_index into int32 rows/cols --------------------------
__global__ void k_decode(const void* __restrict__ ei, int E) {
    int e = blockIdx.x * blockDim.x + threadIdx.x;
    if (e >= E) return;
    if (g_is64) {
        const long long* p = (const long long*)ei;
        g_rows[e] = (int)p[e];
        g_cols[e] = (int)p[E + e];
    } else {
        const int* p = (const int*)ei;
        g_rows[e] = p[e];
        g_cols[e] = p[E + e];
    }
}

// ---------------- per-node init: deg=1 (self loop), cnt=0 ------------------------
__global__ void k_deginit(int n) {
    int i = blockIdx.x * blockDim.x + threadIdx.x;
    if (i < n) { g_deg[i] = 1.0f; g_cnt[i] = 0; }
}

// ---------- edge weight + float deg + int count; smem-staged coalesced load ------
__global__ void k_ewdeg(const float* __restrict__ ea, int E) {
    __shared__ float sea[256 * EF];
    __shared__ float ssm[EF];
    int tid = threadIdx.x;
    if (tid < EF) ssm[tid] = g_sm[tid];
    int base = blockIdx.x * 256;
    int cnt = min(256, E - base);
    int tot = cnt * EF;
    const float* src = ea + (long long)base * EF;
    for (int k = tid; k < tot; k += 256) sea[k] = src[k];
    __syncthreads();
    if (tid >= cnt) return;
    float s = 0.0f;
#pragma unroll
    for (int j = 0; j < EF; j++) s += sea[tid * EF + j] * ssm[j];
    int e = base + tid;
    g_ew[e] = s;
    int c = g_cols[e];
    atomicAdd(&g_deg[c], s);
    atomicAdd(&g_cnt[c], 1);
}

// ---------------- deg^{-1/2} and self-loop norm -----------------------------------
__global__ void k_dinv(int n) {
    int i = blockIdx.x * blockDim.x + threadIdx.x;
    if (i >= n) return;
    float di = rsqrtf(g_deg[i]);   // deg >= 1 always
    g_dinv[i] = di;
    g_dsq[i] = di * di;
}

// ---------------- scan stage A: per-block sums of g_cnt ---------------------------
__global__ void k_scanA(int n) {
    __shared__ int sm[SCAN_B];
    int i = blockIdx.x * SCAN_B + threadIdx.x;
    sm[threadIdx.x] = (i < n) ? g_cnt[i] : 0;
    __syncthreads();
    for (int off = SCAN_B / 2; off > 0; off >>= 1) {
        if (threadIdx.x < off) sm[threadIdx.x] += sm[threadIdx.x + off];
        __syncthreads();
    }
    if (threadIdx.x == 0) g_bsum[blockIdx.x] = sm[0];
}

// ---------------- scan stage B: exclusive scan of block sums ----------------------
__global__ void k_scanB(int nblk) {
    if (threadIdx.x == 0) {
        int run = 0;
        for (int i = 0; i < nblk; i++) { g_boff[i] = run; run += g_bsum[i]; }
    }
}

// ---------------- scan stage C: in-block exclusive scan + base; init cursor -------
__global__ void k_scanC(int n) {
    __shared__ int sm[SCAN_B];
    int i = blockIdx.x * SCAN_B + threadIdx.x;
    int v = (i < n) ? g_cnt[i] : 0;
    sm[threadIdx.x] = v;
    __syncthreads();
    for (int off = 1; off < SCAN_B; off <<= 1) {
        int t = (threadIdx.x >= off) ? sm[threadIdx.x - off] : 0;
        __syncthreads();
        sm[threadIdx.x] += t;
        __syncthreads();
    }
    if (i < n) {
        int st = g_boff[blockIdx.x] + sm[threadIdx.x] - v;  // exclusive
        g_start[i] = st;
        g_cursor[i] = st;
    }
}

// ---------------- CSR build: pack (row, norm) sorted by destination ---------------
__global__ void k_build(int E) {
    int e = blockIdx.x * blockDim.x + threadIdx.x;
    if (e >= E) return;
    int r = g_rows[e];
    int c = g_cols[e];
    float nrm = g_dinv[r] * g_ew[e] * g_dinv[c];
    int pos = atomicAdd(&g_cursor[c], 1);
    g_edge[pos] = make_uint2((unsigned)r, __float_as_uint(nrm));
}

// ---------------- GEMM: h = x @ W  (thread per row, W in smem) --------------------
__global__ void k_gemm(const float* __restrict__ xext, int sel,
                       const float* __restrict__ W, int n) {
    __shared__ float Ws[D * D];
    for (int i = threadIdx.x; i < D * D; i += blockDim.x) Ws[i] = W[i];
    __syncthreads();

    const float* x = (sel == 0) ? xext : ((sel == 1) ? g_bufA : g_bufB);
    int row = blockIdx.x * blockDim.x + threadIdx.x;
    if (row >= n) return;

    const float4* xr = (const float4*)(x + (long long)row * D);
    float4 acc[16];
#pragma unroll
    for (int c = 0; c < 16; c++) acc[c] = make_float4(0.f, 0.f, 0.f, 0.f);

#pragma unroll
    for (int k4 = 0; k4 < 16; k4++) {
        float4 xv = xr[k4];
        float xa[4] = {xv.x, xv.y, xv.z, xv.w};
#pragma unroll
        for (int kk = 0; kk < 4; kk++) {
            float xk = xa[kk];
            const float4* wrow = (const float4*)&Ws[(k4 * 4 + kk) * D];
#pragma unroll
            for (int c = 0; c < 16; c++) {
                float4 wv = wrow[c];
                acc[c].x += xk * wv.x;
                acc[c].y += xk * wv.y;
                acc[c].z += xk * wv.z;
                acc[c].w += xk * wv.w;
            }
        }
    }
    float4* ho = (float4*)(g_h + (long long)row * D);
#pragma unroll
    for (int c = 0; c < 16; c++) ho[c] = acc[c];
}

// ------ fused CSR aggregate (+self loop) + bias + relu + attention pool -----------
// warp per node (grid-stride); no atomics on node features; block-reduced pool.
__global__ void k_aggpool(int sel_out, const float* __restrict__ b,
                          const float* __restrict__ wg,
                          const float* __restrict__ bg,
                          int layer, int n) {
    __shared__ float ps0[8][32];
    __shared__ float ps1[8][32];
    __shared__ float pz[8];
    float* xo = (sel_out == 1) ? g_bufA : g_bufB;
    int lane = threadIdx.x & 31;
    int wlocal = threadIdx.x >> 5;              // 0..7
    int warp = (blockIdx.x * blockDim.x + threadIdx.x) >> 5;
    int nwarps = (gridDim.x * blockDim.x) >> 5;

    float wg0 = wg[lane], wg1 = wg[lane + 32];
    float b0 = b[lane],  b1 = b[lane + 32];
    float bgv = bg[0];

    float s0 = 0.f, s1 = 0.f, z = 0.f;

    for (int i = warp; i < n; i += nwarps) {
        const float* hi = g_h + (long long)i * D;
        float ds = g_dsq[i];
        float acc0 = ds * hi[lane];
        float acc1 = ds * hi[lane + 32];

        int j = g_start[i];
        int end = j + g_cnt[i];
        // 2-edge unrolled gather
        for (; j + 1 < end; j += 2) {
            uint2 p0 = __ldg(&g_edge[j]);
            uint2 p1 = __ldg(&g_edge[j + 1]);
            const float* h0 = g_h + (long long)p0.x * D;
            const float* h1 = g_h + (long long)p1.x * D;
            float n0 = __uint_as_float(p0.y);
            float n1 = __uint_as_float(p1.y);
            float a0 = h0[lane], a1 = h0[lane + 32];
            float c0 = h1[lane], c1 = h1[lane + 32];
            acc0 = fmaf(n0, a0, acc0);
            acc1 = fmaf(n0, a1, acc1);
            acc0 = fmaf(n1, c0, acc0);
            acc1 = fmaf(n1, c1, acc1);
        }
        if (j < end) {
            uint2 p0 = __ldg(&g_edge[j]);
            const float* h0 = g_h + (long long)p0.x * D;
            float n0 = __uint_as_float(p0.y);
            acc0 = fmaf(n0, h0[lane], acc0);
            acc1 = fmaf(n0, h0[lane + 32], acc1);
        }

        float v0 = fmaxf(acc0 + b0, 0.f);
        float v1 = fmaxf(acc1 + b1, 0.f);
        long long idx = (long long)i * D + lane;
        xo[idx] = v0;
        xo[idx + 32] = v1;

        float dot = v0 * wg0 + v1 * wg1;
#pragma unroll
        for (int off = 16; off > 0; off >>= 1)
            dot += __shfl_xor_sync(0xffffffffu, dot, off);
        float sg = 1.0f / (1.0f + expf(-(dot + bgv)));  // sigmoid gate
        float w = expf(sg);                             // softmax numerator
        s0 += w * v0;
        s1 += w * v1;
        if (lane == 0) z += w;
    }

    // block-level reduction of pool partials, then one atomic set per block
    ps0[wlocal][lane] = s0;
    ps1[wlocal][lane] = s1;
    if (lane == 0) pz[wlocal] = z;
    __syncthreads();
    if (wlocal == 0) {
        float t0 = 0.f, t1 = 0.f, tz = 0.f;
#pragma unroll
        for (int w8 = 0; w8 < 8; w8++) {
            t0 += ps0[w8][lane];
            t1 += ps1[w8][lane];
            if (lane == 0) tz += pz[w8];
        }
        atomicAdd(&g_S[layer * D + lane], t0);
        atomicAdd(&g_S[layer * D + lane + 32], t1);
        if (lane == 0) atomicAdd(&g_Z[layer], tz);
    }
}

// ---------------- final divide ----------------------------------------------------
__global__ void k_out(float* __restrict__ out) {
    int t = threadIdx.x;
    if (t < 3 * D) out[t] = g_S[t] / g_Z[t / D];
}

// ---------------- launch ----------------------------------------------------------
extern "C" void kernel_launch(void* const* d_in, const int* in_sizes, int n_in,
                              void* d_out, int out_size) {
    const float* x     = (const float*)d_in[0];
    const void*  ei    = d_in[1];
    const float* ea    = (const float*)d_in[2];
    const float* aaaaa = (const float*)d_in[3];
    const float* W[3]  = {(const float*)d_in[4], (const float*)d_in[6], (const float*)d_in[8]};
    const float* b[3]  = {(const float*)d_in[5], (const float*)d_in[7], (const float*)d_in[9]};
    const float* wg[3] = {(const float*)d_in[10], (const float*)d_in[12], (const float*)d_in[14]};
    const float* bg[3] = {(const float*)d_in[11], (const float*)d_in[13], (const float*)d_in[15]};
    float* out = (float*)d_out;

    int N = in_sizes[0] / D;     // 100000
    int E = in_sizes[2] / EF;    // 1250000
    int nblk = (N + SCAN_B - 1) / SCAN_B;

    k_init<<<1, 256>>>(aaaaa, (const int*)ei);
    k_decode<<<(E + 255) / 256, 256>>>(ei, E);
    k_deginit<<<(N + 255) / 256, 256>>>(N);
    k_ewdeg<<<(E + 255) / 256, 256>>>(ea, E);
    k_dinv<<<(N + 255) / 256, 256>>>(N);
    k_scanA<<<nblk, SCAN_B>>>(N);
    k_scanB<<<1, 32>>>(nblk);
    k_scanC<<<nblk, SCAN_B>>>(N);
    k_build<<<(E + 255) / 256, 256>>>(E);

    // layer 1: x(ext) -> bufA, pool 0
    k_gemm<<<(N + 127) / 128, 128>>>(x, 0, W[0], N);
    k_aggpool<<<1024, 256>>>(1, b[0], wg[0], bg[0], 0, N);
    // layer 2: bufA -> bufB, pool 1
    k_gemm<<<(N + 127) / 128, 128>>>(x, 1, W[1], N);
    k_aggpool<<<1024, 256>>>(2, b[1], wg[1], bg[1], 1, N);
    // layer 3: bufB -> bufA, pool 2
    k_gemm<<<(N + 127) / 128, 128>>>(x, 2, W[2], N);
    k_aggpool<<<1024, 256>>>(1, b[2], wg[2], bg[2], 2, N);

    k_out<<<1, 192>>>(out);
}